// round 9
// baseline (speedup 1.0000x reference)
#include <cuda_runtime.h>

// NablaT 3D: out[z,y,x] = bdiff_z(x0) + bdiff_y(x1) + bdiff_x(x2)
// bdiff along dim d: out[i] = a - b, a = (i>0)? v[i-1] : 0, b = (i<S-1)? v[i] : 0
//
// x: [3, 320, 320, 320] fp32. out: [320,320,320] fp32. Traffic floor ~501 MB.
// Persistent grid-stride form: exact-residency launch (148 SMs x 8 CTAs x 256
// threads), each thread loops over float4 elements with stride = gridDim*256.
// Mechanism: removes ~27 CTA-wave ramp/drain transients so DRAM request
// pressure stays saturated for the whole kernel. __stcs keeps the write-once
// output out of L2 (preserves z-1/y-1 halo dedup that holds traffic at floor).

#define S 320
#define PLANE (S * S)           // 102400
#define VOL   (S * S * S)       // 32768000
#define X4    (S / 4)           // 80
#define P4    (PLANE / 4)       // 25600
#define NV4   (VOL / 4)         // 8192000 float4 outputs

#define NBLK  1184              // 148 SMs * 8 resident CTAs
#define NTHR  256

__global__ __launch_bounds__(NTHR)
void nablat_kernel(const float* __restrict__ xin, float* __restrict__ out) {
    const unsigned stride = NBLK * NTHR;                  // 303104
    unsigned t = blockIdx.x * (unsigned)NTHR + threadIdx.x;

    const float4* __restrict__ p0 = (const float4*)(xin);
    const float4* __restrict__ p1 = (const float4*)(xin + (long)VOL);
    const float4* __restrict__ p2 = (const float4*)(xin + 2L * VOL);
    const float*  __restrict__ s2 = xin + 2L * VOL;
    float4* __restrict__ o4 = (float4*)out;

    const float4 zero = make_float4(0.f, 0.f, 0.f, 0.f);

    for (; t < NV4; t += stride) {
        const unsigned x4  = t % X4;
        const unsigned rem = t / X4;
        const unsigned y   = rem % S;
        const unsigned z   = rem / S;

        // axis 0 (z): a0 = x0[z-1], b0 = x0[z]
        float4 b0 = (z < S - 1) ? __ldg(&p0[t])      : zero;
        float4 a0 = (z > 0)     ? __ldg(&p0[t - P4]) : zero;

        // axis 1 (y): a1 = x1[y-1], b1 = x1[y]
        float4 b1 = (y < S - 1) ? __ldg(&p1[t])      : zero;
        float4 a1 = (y > 0)     ? __ldg(&p1[t - X4]) : zero;

        // axis 2 (x): within-vector shift; left-halo scalar (L1/L2 hit)
        float4 v2   = __ldg(&p2[t]);
        float  prev = (x4 > 0) ? __ldg(&s2[(long)t * 4 - 1]) : 0.f;
        float  b2w  = (x4 == X4 - 1) ? 0.f : v2.w;

        float4 o;
        o.x = (a0.x - b0.x) + (a1.x - b1.x) + (prev - v2.x);
        o.y = (a0.y - b0.y) + (a1.y - b1.y) + (v2.x - v2.y);
        o.z = (a0.z - b0.z) + (a1.z - b1.z) + (v2.y - v2.z);
        o.w = (a0.w - b0.w) + (a1.w - b1.w) + (v2.z - b2w);

        __stcs(&o4[t], o);   // streaming: output never re-read
    }
}

extern "C" void kernel_launch(void* const* d_in, const int* in_sizes, int n_in,
                              void* d_out, int out_size) {
    const float* x = (const float*)d_in[0];
    float* out = (float*)d_out;

    nablat_kernel<<<NBLK, NTHR>>>(x, out);
}

// round 10
// speedup vs baseline: 1.0774x; 1.0774x over previous
#include <cuda_runtime.h>

// NablaT 3D: out[z,y,x] = bdiff_z(x0) + bdiff_y(x1) + bdiff_x(x2)
// bdiff along dim d: out[i] = a - b, a = (i>0)? v[i-1] : 0, b = (i<S-1)? v[i] : 0
//
// x: [3, 320, 320, 320] fp32. out: [320,320,320] fp32.
// FINAL (measured-best across 9 variants, R3 verbatim): one thread per float4,
// flat 256-thread blocks, exact-fit grid. 32 regs, 100% theoretical occupancy.
// At the memory roofline: ~6.9 TB/s (87% of spec), traffic at the 524 MB floor.
// Tested and rejected: z-unroll (occupancy loss), shuffle halo + __ldcs
// (L2 halo-dedup loss), 512-thread blocks (granularity), persistent grid-stride
// (serialized MLP). __stcs was neutral; plain store kept (best wall time).

#define S 320
#define PLANE (S * S)           // 102400
#define VOL   (S * S * S)       // 32768000
#define X4    (S / 4)           // 80
#define P4    (PLANE / 4)       // 25600
#define NV4   (VOL / 4)         // 8192000 float4 outputs

__global__ __launch_bounds__(256)
void nablat_kernel(const float* __restrict__ xin, float* __restrict__ out) {
    const unsigned t = blockIdx.x * 256u + threadIdx.x;  // flat float4 index == [z,y,x4]

    const unsigned x4  = t % X4;
    const unsigned rem = t / X4;
    const unsigned y   = rem % S;
    const unsigned z   = rem / S;
    const unsigned xi  = x4 * 4;

    const float4* __restrict__ p0 = (const float4*)(xin);
    const float4* __restrict__ p1 = (const float4*)(xin + (long)VOL);
    const float4* __restrict__ p2 = (const float4*)(xin + 2L * VOL);
    const float*  __restrict__ s2 = xin + 2L * VOL;

    const float4 zero = make_float4(0.f, 0.f, 0.f, 0.f);

    // axis 0 (z): a0 = x0[z-1], b0 = x0[z] (b zeroed at z==S-1)
    float4 b0 = (z < S - 1) ? __ldg(&p0[t])      : zero;
    float4 a0 = (z > 0)     ? __ldg(&p0[t - P4]) : zero;

    // axis 1 (y): a1 = x1[y-1], b1 = x1[y]
    float4 b1 = (y < S - 1) ? __ldg(&p1[t])      : zero;
    float4 a1 = (y > 0)     ? __ldg(&p1[t - X4]) : zero;

    // axis 2 (x): within-vector shift; left-halo scalar at xi-1 (L1/L2 hit)
    float4 v2   = __ldg(&p2[t]);
    float  prev = (xi > 0) ? __ldg(&s2[(long)t * 4 - 1]) : 0.f;
    float  b2w  = (x4 == X4 - 1) ? 0.f : v2.w;   // x == S-1 boundary

    float4 o;
    o.x = (a0.x - b0.x) + (a1.x - b1.x) + (prev - v2.x);
    o.y = (a0.y - b0.y) + (a1.y - b1.y) + (v2.x - v2.y);
    o.z = (a0.z - b0.z) + (a1.z - b1.z) + (v2.y - v2.z);
    o.w = (a0.w - b0.w) + (a1.w - b1.w) + (v2.z - b2w);

    ((float4*)out)[t] = o;
}

extern "C" void kernel_launch(void* const* d_in, const int* in_sizes, int n_in,
                              void* d_out, int out_size) {
    const float* x = (const float*)d_in[0];
    float* out = (float*)d_out;

    nablat_kernel<<<NV4 / 256, 256>>>(x, out);   // 32000 blocks, exact fit
}

// round 11
// speedup vs baseline: 1.0810x; 1.0034x over previous
#include <cuda_runtime.h>

// NablaT 3D: out[z,y,x] = bdiff_z(x0) + bdiff_y(x1) + bdiff_x(x2)
// bdiff along dim d: out[i] = a - b, a = (i>0)? v[i-1] : 0, b = (i<S-1)? v[i] : 0
//
// x: [3, 320, 320, 320] fp32. out: [320,320,320] fp32. Traffic floor ~524 MB.
// R3 measured-best form with ONE change: flat 128-thread blocks (finer CTA
// granularity -> better work-distributor backfill -> higher achieved occupancy
// and sustained DRAM request pressure). 32 regs, 64 warps/SM theoretical.
// Session-tested and rejected: z-unroll, shuffle halo, __ldcs, __stcs,
// 512-thread blocks, persistent grid-stride. Kernel is at the HBM roofline
// (~87% of 8 TB/s spec).

#define S 320
#define PLANE (S * S)           // 102400
#define VOL   (S * S * S)       // 32768000
#define X4    (S / 4)           // 80
#define P4    (PLANE / 4)       // 25600
#define NV4   (VOL / 4)         // 8192000 float4 outputs

__global__ __launch_bounds__(128)
void nablat_kernel(const float* __restrict__ xin, float* __restrict__ out) {
    const unsigned t = blockIdx.x * 128u + threadIdx.x;  // flat float4 index == [z,y,x4]

    const unsigned x4  = t % X4;
    const unsigned rem = t / X4;
    const unsigned y   = rem % S;
    const unsigned z   = rem / S;
    const unsigned xi  = x4 * 4;

    const float4* __restrict__ p0 = (const float4*)(xin);
    const float4* __restrict__ p1 = (const float4*)(xin + (long)VOL);
    const float4* __restrict__ p2 = (const float4*)(xin + 2L * VOL);
    const float*  __restrict__ s2 = xin + 2L * VOL;

    const float4 zero = make_float4(0.f, 0.f, 0.f, 0.f);

    // axis 0 (z): a0 = x0[z-1], b0 = x0[z] (b zeroed at z==S-1)
    float4 b0 = (z < S - 1) ? __ldg(&p0[t])      : zero;
    float4 a0 = (z > 0)     ? __ldg(&p0[t - P4]) : zero;

    // axis 1 (y): a1 = x1[y-1], b1 = x1[y]
    float4 b1 = (y < S - 1) ? __ldg(&p1[t])      : zero;
    float4 a1 = (y > 0)     ? __ldg(&p1[t - X4]) : zero;

    // axis 2 (x): within-vector shift; left-halo scalar at xi-1 (L1/L2 hit)
    float4 v2   = __ldg(&p2[t]);
    float  prev = (xi > 0) ? __ldg(&s2[(long)t * 4 - 1]) : 0.f;
    float  b2w  = (x4 == X4 - 1) ? 0.f : v2.w;   // x == S-1 boundary

    float4 o;
    o.x = (a0.x - b0.x) + (a1.x - b1.x) + (prev - v2.x);
    o.y = (a0.y - b0.y) + (a1.y - b1.y) + (v2.x - v2.y);
    o.z = (a0.z - b0.z) + (a1.z - b1.z) + (v2.y - v2.z);
    o.w = (a0.w - b0.w) + (a1.w - b1.w) + (v2.z - b2w);

    ((float4*)out)[t] = o;
}

extern "C" void kernel_launch(void* const* d_in, const int* in_sizes, int n_in,
                              void* d_out, int out_size) {
    const float* x = (const float*)d_in[0];
    float* out = (float*)d_out;

    nablat_kernel<<<NV4 / 128, 128>>>(x, out);   // 64000 blocks, exact fit
}